// round 15
// baseline (speedup 1.0000x reference)
#include <cuda_runtime.h>
#include <cuda_fp16.h>
#include <cstdint>

#define Bb 16
#define Nn 2048
#define Cc 512
#define K3 1536

// ---------------- device scratch ----------------
__device__ __half g_wh  [1536*1536];   // fp16 Weff [br*512+o][t*512+c]
__device__ __half g_w3h [9*512*512];   // fp16 w3 slices [br*3+t][o][i]
__device__ __half g_w1t [3*512*512];   // fp16 w1 transposed [br][c][i]
__device__ __half g_wph [512*512];     // fp16 wproj
__device__ __half g_xh  [16777216];    // [b][n][c] fp16 x
__device__ __half g_qkv [50331648];    // [b][3C][N] (q,k rows used)
__device__ __half g_vt  [16777216];    // [b][n][d]
__device__ __half g_p   [4194304];     // softmax(S) fp16 [b][c][d]
__device__ __half g_ot  [16777216];    // [b][n][c]

// ---------------- PTX helpers ----------------
__device__ __forceinline__ uint32_t s2u(const void* p){
    uint32_t a; asm("{ .reg .u64 t; cvta.to.shared.u64 t, %1; cvt.u32.u64 %0, t; }" : "=r"(a) : "l"(p)); return a;
}
__device__ __forceinline__ void cpa16(uint32_t d, const void* s){
    asm volatile("cp.async.cg.shared.global [%0], [%1], 16;" :: "r"(d), "l"(s));
}
__device__ __forceinline__ void cp_commit(){ asm volatile("cp.async.commit_group;"); }
__device__ __forceinline__ void cp_wait1(){ asm volatile("cp.async.wait_group 1;"); }
__device__ __forceinline__ void cp_wait0(){ asm volatile("cp.async.wait_group 0;"); }
__device__ __forceinline__ void ldsm4(uint32_t& r0, uint32_t& r1, uint32_t& r2, uint32_t& r3, uint32_t a){
    asm volatile("ldmatrix.sync.aligned.m8n8.x4.shared.b16 {%0,%1,%2,%3}, [%4];"
        : "=r"(r0), "=r"(r1), "=r"(r2), "=r"(r3) : "r"(a));
}
__device__ __forceinline__ void mma16816(float* d, const uint32_t* a, uint32_t b0, uint32_t b1){
    asm volatile("mma.sync.aligned.m16n8k16.row.col.f32.f16.f16.f32 "
        "{%0,%1,%2,%3}, {%4,%5,%6,%7}, {%8,%9}, {%0,%1,%2,%3};"
        : "+f"(d[0]), "+f"(d[1]), "+f"(d[2]), "+f"(d[3])
        : "r"(a[0]), "r"(a[1]), "r"(a[2]), "r"(a[3]), "r"(b0), "r"(b1));
}

#define ROWB 80u
#define MATB 10240u

// =====================================================================
// gemm_qkv v2: N-tile 128 for wave-quantization fix (3072 CTAs, 20.76
// waves vs 10.38 -> ceil loss 6% -> 1.2%). x-dedup, CTA M=128 x N=128,
// 256 thr, warp 32x64 (4Mx2N, r9-proven inner loop), 3-stage pipeline.
// v-row CTAs (by>=8) write transposed into g_vt via smem staging.
// =====================================================================
#define QA_OFF  0u
#define QB_OFF  30720u            // 3 * 128 * 80
#define QBUF    41120u            // + 130 * 80
#define Q_SMEM  (3*41120)
#define TR_STRIDE 130             // halves per staged row (128 + 2 pad)

__global__ __launch_bounds__(256, 1) void gemm_qkv() {
    extern __shared__ char smem[];
    uint32_t sb = s2u(smem);
    const int tid  = threadIdx.x;
    const int lane = tid & 31;
    const int wid  = tid >> 5;

    const int b  = blockIdx.z;
    const int m0 = blockIdx.y * 128;
    const int n0 = blockIdx.x * 128;
    const __half* Ap = g_wh + (size_t)m0 * K3;
    const __half* Xb = g_xh + (size_t)b * Nn * Cc;

    const int NK = Cc >> 5;   // 16

    auto load_chunk = [&](int kc) {
        uint32_t base = sb + (uint32_t)(kc % 3) * QBUF;
        int c0 = kc << 5;
        // A: 3 t-slices x 128 rows x 4 units = 1536 units, 6 per thread
        #pragma unroll
        for (int it = 0; it < 6; it++) {
            int u  = tid + it * 256;
            int sl = u >> 9;
            int rm = u & 511;
            int r  = rm >> 2, cu = rm & 3;
            cpa16(base + QA_OFF + (uint32_t)sl*MATB + (uint32_t)r*ROWB + (uint32_t)cu*16u,
                  Ap + (size_t)r * K3 + sl*512 + c0 + cu*8);
        }
        // B: 130 rows x 4 units = 520 units
        #pragma unroll
        for (int it = 0; it < 2; it++) {
            int u = tid + it * 256;          // 0..511
            int r = u >> 2, cu = u & 3;
            int n = n0 + r - 1;
            if (n < 0) n += Nn; else if (n >= Nn) n -= Nn;
            cpa16(base + QB_OFF + (uint32_t)r*ROWB + (uint32_t)cu*16u,
                  Xb + (size_t)n * Cc + c0 + cu*8);
        }
        if (tid < 8) {                        // units 512..519 (rows 128,129)
            int u = 512 + tid;
            int r = u >> 2, cu = u & 3;
            int n = n0 + r - 1;
            if (n >= Nn) n -= Nn;
            cpa16(base + QB_OFF + (uint32_t)r*ROWB + (uint32_t)cu*16u,
                  Xb + (size_t)n * Cc + c0 + cu*8);
        }
        cp_commit();
    };

    float acc[2][8][4];
    #pragma unroll
    for (int i = 0; i < 2; i++)
        #pragma unroll
        for (int j = 0; j < 8; j++)
            #pragma unroll
            for (int q = 0; q < 4; q++) acc[i][j][q] = 0.f;

    const int m0w = (wid >> 1) * 32;       // 4 M warp-groups
    const int n0w = (wid & 1) * 64;        // 2 N warp-groups
    const int l16 = lane & 15, hi = lane >> 4;

    load_chunk(0);
    load_chunk(1);
    for (int kc = 0; kc < NK; kc++) {
        if (kc + 1 < NK) cp_wait1(); else cp_wait0();
        __syncthreads();
        if (kc + 2 < NK) load_chunk(kc + 2);
        uint32_t base = sb + (uint32_t)(kc % 3) * QBUF;
        #pragma unroll
        for (int t = 0; t < 3; t++) {
            uint32_t aB = base + QA_OFF + (uint32_t)t*MATB + (uint32_t)(m0w + l16)*ROWB + (uint32_t)hi*16u;
            uint32_t bB = base + QB_OFF + (uint32_t)(n0w + l16 + t)*ROWB + (uint32_t)hi*16u;
            #pragma unroll
            for (int ks = 0; ks < 2; ks++) {
                uint32_t koff = (uint32_t)ks * 32u;
                uint32_t av[2][4], bv[4][4];
                ldsm4(av[0][0], av[0][1], av[0][2], av[0][3], aB + koff);
                ldsm4(av[1][0], av[1][1], av[1][2], av[1][3], aB + 16*ROWB + koff);
                #pragma unroll
                for (int nt = 0; nt < 4; nt++)
                    ldsm4(bv[nt][0], bv[nt][1], bv[nt][2], bv[nt][3],
                          bB + (uint32_t)nt*16*ROWB + koff);
                #pragma unroll
                for (int mi = 0; mi < 2; mi++) {
                    #pragma unroll
                    for (int nj = 0; nj < 8; nj++) {
                        int nt = nj >> 1, sel = nj & 1;
                        uint32_t b0 = sel ? bv[nt][1] : bv[nt][0];
                        uint32_t b1 = sel ? bv[nt][3] : bv[nt][2];
                        mma16816(acc[mi][nj], av[mi], b0, b1);
                    }
                }
            }
        }
    }

    if (blockIdx.y < 8) {
        const int rowBase = m0 + m0w + (lane >> 2);
        const int colBase = n0 + n0w + (lane & 3) * 2;
        __half* C = g_qkv + (size_t)b * K3 * Nn;
        #pragma unroll
        for (int mi = 0; mi < 2; mi++) {
            #pragma unroll
            for (int nj = 0; nj < 8; nj++) {
                int c = colBase + nj * 8;
                #pragma unroll
                for (int half = 0; half < 2; half++) {
                    int r = rowBase + mi * 16 + half * 8;
                    *(__half2*)(C + (size_t)r * Nn + c) =
                        __halves2half2(__float2half_rn(acc[mi][nj][half*2]),
                                       __float2half_rn(acc[mi][nj][half*2+1]));
                }
            }
        }
    } else {
        // v rows: transpose via smem, write vt[b][n][d] coalesced
        __syncthreads();
        __half* sEp = (__half*)smem;          // [128 d][TR_STRIDE n]
        const int rowL = m0w + (lane >> 2);
        const int colL = n0w + (lane & 3) * 2;
        #pragma unroll
        for (int mi = 0; mi < 2; mi++) {
            #pragma unroll
            for (int nj = 0; nj < 8; nj++) {
                int c = colL + nj * 8;
                #pragma unroll
                for (int half = 0; half < 2; half++) {
                    int r = rowL + mi * 16 + half * 8;
                    *(__half2*)(sEp + (size_t)r * TR_STRIDE + c) =
                        __halves2half2(__float2half_rn(acc[mi][nj][half*2]),
                                       __float2half_rn(acc[mi][nj][half*2+1]));
                }
            }
        }
        __syncthreads();
        const int d0 = m0 - 1024;             // 0,128,256,384
        __half* VT = g_vt + (size_t)b * Nn * Cc;
        const int nsub = tid >> 6;            // 0..3
        const int d2   = tid & 63;            // half2 index over 128 d-rows
        #pragma unroll 4
        for (int it = 0; it < 32; it++) {
            int n = it * 4 + nsub;            // 0..127
            __half h0 = sEp[(size_t)(2*d2)   * TR_STRIDE + n];
            __half h1 = sEp[(size_t)(2*d2+1) * TR_STRIDE + n];
            *(__half2*)(VT + (size_t)(n0 + n) * Cc + d0 + 2*d2) = __halves2half2(h0, h1);
        }
    }
}

// =====================================================================
// scores_softmax (r12 config): fused S=(1/C)q.k^T + softmax -> P fp16.
// CTA 64 x 512, 512 threads (2Mx8N), 3-stage pipeline. Grid 128 CTAs.
// =====================================================================
#define SS_AOFF 0u
#define SS_BOFF 5120u
#define SS_BUF  46080u
#define SS_SMEM (3*46080)

__global__ __launch_bounds__(512, 1) void scores_softmax() {
    extern __shared__ char smem[];
    uint32_t sb = s2u(smem);
    const int tid  = threadIdx.x;
    const int lane = tid & 31;
    const int wid  = tid >> 5;

    const int b  = blockIdx.y;
    const int m0 = blockIdx.x * 64;
    const __half* Ap = g_qkv + (size_t)b * K3 * Nn + (size_t)m0 * Nn;
    const __half* Bp = g_qkv + (size_t)b * K3 * Nn + (size_t)512 * Nn;

    const int NK = Nn >> 5;   // 64

    auto load_chunk = [&](int kc) {
        uint32_t base = sb + (uint32_t)(kc % 3) * SS_BUF;
        int ko = kc << 5;
        #pragma unroll
        for (int it = 0; it < 4; it++) {
            int u = tid + it * 512;
            int r = u >> 2, cu = u & 3;
            cpa16(base + SS_BOFF + (uint32_t)r*ROWB + (uint32_t)cu*16u,
                  Bp + (size_t)r * Nn + ko + cu*8);
        }
        if (tid < 256) {
            int r = tid >> 2, cu = tid & 3;
            cpa16(base + SS_AOFF + (uint32_t)r*ROWB + (uint32_t)cu*16u,
                  Ap + (size_t)r * Nn + ko + cu*8);
        }
        cp_commit();
    };

    float acc[2][8][4];
    #pragma unroll
    for (int i = 0; i < 2; i++)
        #pragma unroll
        for (int j = 0; j < 8; j++)
            #pragma unroll
            for (int q = 0; q < 4; q++) acc[i][j][q] = 0.f;

    const int m0w = (wid >> 3) * 32;
    const int n0w = (wid & 7) * 64;
    const int l16 = lane & 15, hi = lane >> 4;

    load_chunk(0);
    load_chunk(1);
    for (int kc = 0; kc < NK; kc++) {
        if (kc + 1 < NK) cp_wait1(); else cp_wait0();
        __syncthreads();
        if (kc + 2 < NK) load_chunk(kc + 2);
        uint32_t base = sb + (uint32_t)(kc % 3) * SS_BUF;
        uint32_t aAddr = base + SS_AOFF + (uint32_t)(m0w + l16) * ROWB + (uint32_t)hi * 16u;
        uint32_t bAddr = base + SS_BOFF + (uint32_t)(n0w + l16) * ROWB + (uint32_t)hi * 16u;
        #pragma unroll
        for (int ks = 0; ks < 2; ks++) {
            uint32_t koff = (uint32_t)ks * 32u;
            uint32_t av[2][4], bv[4][4];
            ldsm4(av[0][0], av[0][1], av[0][2], av[0][3], aAddr + koff);
            ldsm4(av[1][0], av[1][1], av[1][2], av[1][3], aAddr + 16*ROWB + koff);
            #pragma unroll
            for (int nt = 0; nt < 4; nt++)
                ldsm4(bv[nt][0], bv[nt][1], bv[nt][2], bv[nt][3], bAddr + (uint32_t)nt*16*ROWB + koff);
            #pragma unroll
            for (int mi = 0; mi < 2; mi++) {
                #pragma unroll
                for (int nj = 0; nj < 8; nj++) {
                    int nt = nj >> 1, sel = nj & 1;
                    uint32_t b0 = sel ? bv[nt][1] : bv[nt][0];
                    uint32_t b1 = sel ? bv[nt][3] : bv[nt][2];
                    mma16816(acc[mi][nj], av[mi], b0, b1);
                }
            }
        }
    }

    const float scale = 1.0f / (float)Cc;
    #pragma unroll
    for (int mi = 0; mi < 2; mi++)
        #pragma unroll
        for (int nj = 0; nj < 8; nj++)
            #pragma unroll
            for (int q = 0; q < 4; q++) acc[mi][nj][q] *= scale;

    float rmax[4];
    #pragma unroll
    for (int j = 0; j < 4; j++) {
        int mi = j >> 1, half = j & 1;
        float m = -1e30f;
        #pragma unroll
        for (int nj = 0; nj < 8; nj++) {
            m = fmaxf(m, acc[mi][nj][half*2]);
            m = fmaxf(m, acc[mi][nj][half*2+1]);
        }
        rmax[j] = m;
    }
    #pragma unroll
    for (int j = 0; j < 4; j++) {
        rmax[j] = fmaxf(rmax[j], __shfl_xor_sync(0xffffffffu, rmax[j], 1));
        rmax[j] = fmaxf(rmax[j], __shfl_xor_sync(0xffffffffu, rmax[j], 2));
    }
    __syncthreads();
    float* redm = (float*)smem;
    float* reds = (float*)(smem + 4096);
    if ((lane & 3) == 0) {
        #pragma unroll
        for (int j = 0; j < 4; j++) {
            int row = m0w + (lane >> 2) + (j >> 1) * 16 + (j & 1) * 8;
            redm[row * 8 + (wid & 7)] = rmax[j];
        }
    }
    __syncthreads();
    float rM[4];
    #pragma unroll
    for (int j = 0; j < 4; j++) {
        int row = m0w + (lane >> 2) + (j >> 1) * 16 + (j & 1) * 8;
        float m = redm[row * 8];
        #pragma unroll
        for (int g = 1; g < 8; g++) m = fmaxf(m, redm[row * 8 + g]);
        rM[j] = m;
    }
    float rsum[4] = {0.f, 0.f, 0.f, 0.f};
    #pragma unroll
    for (int mi = 0; mi < 2; mi++) {
        #pragma unroll
        for (int half = 0; half < 2; half++) {
            int j = mi * 2 + half;
            #pragma unroll
            for (int nj = 0; nj < 8; nj++) {
                float e0 = __expf(acc[mi][nj][half*2]   - rM[j]);
                float e1 = __expf(acc[mi][nj][half*2+1] - rM[j]);
                acc[mi][nj][half*2]   = e0;
                acc[mi][nj][half*2+1] = e1;
                rsum[j] += e0 + e1;
            }
        }
    }
    #pragma unroll
    for (int j = 0; j < 4; j++) {
        rsum[j] += __shfl_xor_sync(0xffffffffu, rsum[j], 1);
        rsum[j] += __shfl_xor_sync(0xffffffffu, rsum[j], 2);
    }
    if ((lane & 3) == 0) {
        #pragma unroll
        for (int j = 0; j < 4; j++) {
            int row = m0w + (lane >> 2) + (j >> 1) * 16 + (j & 1) * 8;
            reds[row * 8 + (wid & 7)] = rsum[j];
        }
    }
    __syncthreads();
    float rInv[4];
    #pragma unroll
    for (int j = 0; j < 4; j++) {
        int row = m0w + (lane >> 2) + (j >> 1) * 16 + (j & 1) * 8;
        float s = 0.f;
        #pragma unroll
        for (int g = 0; g < 8; g++) s += reds[row * 8 + g];
        rInv[j] = 1.0f / s;
    }
    __half* P = g_p + (size_t)b * Cc * Cc;
    const int rowBase = m0 + m0w + (lane >> 2);
    const int colBase = n0w + (lane & 3) * 2;
    #pragma unroll
    for (int mi = 0; mi < 2; mi++) {
        #pragma unroll
        for (int nj = 0; nj < 8; nj++) {
            int c = colBase + nj * 8;
            #pragma unroll
            for (int half = 0; half < 2; half++) {
                int j = mi * 2 + half;
                int r = rowBase + mi * 16 + half * 8;
                *(__half2*)(P + (size_t)r * Cc + c) =
                    __halves2half2(__float2half_rn(acc[mi][nj][half*2]   * rInv[j]),
                                   __float2half_rn(acc[mi][nj][half*2+1] * rInv[j]));
            }
        }
    }
}

// =====================================================================
// gemm1: generic plain-fp16 GEMM, 3-stage single-sync, 2 CTAs/SM.
// =====================================================================
#define BUF1 20480u
#define G1_SMEM (3*20480)

struct G1Args {
    const __half* A; const __half* B;
    long long sA, sB, sC;
    int lda, ldb, ldc, K;
    float* Cf; __half* Ch;
    const float* bias;
    float scale;
};

__global__ __launch_bounds__(256, 2) void gemm1(const G1Args g) {
    extern __shared__ char smem[];
    uint32_t sb = s2u(smem);
    const int tid  = threadIdx.x;
    const int lane = tid & 31;
    const int wid  = tid >> 5;

    const int b  = blockIdx.z;
    const int m0 = blockIdx.y * 128;
    const int n0 = blockIdx.x * 128;
    const __half* Ap = g.A + (long long)b * g.sA + (long long)m0 * g.lda;
    const __half* Bp = g.B + (long long)b * g.sB + (long long)n0 * g.ldb;

    const int NK = g.K >> 5;

    auto load_chunk = [&](int kc) {
        uint32_t base = sb + (uint32_t)(kc % 3) * BUF1;
        int ko = kc << 5;
        #pragma unroll
        for (int it = 0; it < 2; it++) {
            int u = tid + it * 256;
            int r = u >> 2, cu = u & 3;
            uint32_t off = (uint32_t)r * ROWB + (uint32_t)cu * 16u;
            cpa16(base + off,        Ap + (size_t)r * g.lda + ko + cu * 8);
            cpa16(base + MATB + off, Bp + (size_t)r * g.ldb + ko + cu * 8);
        }
        cp_commit();
    };

    float acc[2][8][4];
    #pragma unroll
    for (int i = 0; i < 2; i++)
        #pragma unroll
        for (int j = 0; j < 8; j++)
            #pragma unroll
            for (int q = 0; q < 4; q++) acc[i][j][q] = 0.f;

    const int m0w = (wid >> 1) * 32;
    const int n0w = (wid & 1) * 64;
    const int l16 = lane & 15, hi = lane >> 4;

    load_chunk(0);
    load_chunk(1);
    for (int kc = 0; kc < NK; kc++) {
        if (kc + 1 < NK) cp_wait1(); else cp_wait0();
        __syncthreads();
        if (kc + 2 < NK) load_chunk(kc + 2);
        uint32_t base = sb + (uint32_t)(kc % 3) * BUF1;
        uint32_t aAddr = base + (uint32_t)(m0w + l16) * ROWB + (uint32_t)hi * 16u;
        uint32_t bAddr = base + MATB + (uint32_t)(n0w + l16) * ROWB + (uint32_t)hi * 16u;
        #pragma unroll
        for (int ks = 0; ks < 2; ks++) {
            uint32_t koff = (uint32_t)ks * 32u;
            uint32_t av[2][4], bv[4][4];
            ldsm4(av[0][0], av[0][1], av[0][2], av[0][3], aAddr + koff);
            ldsm4(av[1][0], av[1][1], av[1][2], av[1][3], aAddr + 16*ROWB + koff);
            #pragma unroll
            for (int nt = 0; nt < 4; nt++)
                ldsm4(bv[nt][0], bv[nt][1], bv[nt][2], bv[nt][3], bAddr + (uint32_t)nt*16*ROWB + koff);
            #pragma unroll
            for (int mi = 0; mi < 2; mi++) {
                #pragma unroll
                for (int nj = 0; nj < 8; nj++) {
                    int nt = nj >> 1, sel = nj & 1;
                    uint32_t b0 = sel ? bv[nt][1] : bv[nt][0];
                    uint32_t b1 = sel ? bv[nt][3] : bv[nt][2];
                    mma16816(acc[mi][nj], av[mi], b0, b1);
                }
            }
        }
    }

    const int rowBase = m0 + m0w + (lane >> 2);
    const int colBase = n0 + n0w + (lane & 3) * 2;
    if (g.Cf) {
        float* C = g.Cf + (long long)b * g.sC;
        #pragma unroll
        for (int mi = 0; mi < 2; mi++) {
            #pragma unroll
            for (int nj = 0; nj < 8; nj++) {
                int c = colBase + nj * 8;
                #pragma unroll
                for (int half = 0; half < 2; half++) {
                    int r = rowBase + mi * 16 + half * 8;
                    float2 v;
                    v.x = acc[mi][nj][half*2 + 0] * g.scale;
                    v.y = acc[mi][nj][half*2 + 1] * g.scale;
                    if (g.bias) { v.x += g.bias[c]; v.y += g.bias[c + 1]; }
                    *(float2*)(C + (long long)r * g.ldc + c) = v;
                }
            }
        }
    } else {
        __half* C = g.Ch + (long long)b * g.sC;
        #pragma unroll
        for (int mi = 0; mi < 2; mi++) {
            #pragma unroll
            for (int nj = 0; nj < 8; nj++) {
                int c = colBase + nj * 8;
                #pragma unroll
                for (int half = 0; half < 2; half++) {
                    int r = rowBase + mi * 16 + half * 8;
                    *(__half2*)(C + (long long)r * g.ldc + c) =
                        __halves2half2(__float2half_rn(acc[mi][nj][half*2]),
                                       __float2half_rn(acc[mi][nj][half*2+1]));
                }
            }
        }
    }
}

// =====================================================================
// gemm_weff: weff[(br*512+o)][t*512+c] = sum_i w3h[z][o][i] * w1t[br][c][i]
// HMMA, grid (4,4,9) = 144 CTAs, 2/SM, single wave.
// =====================================================================
__global__ __launch_bounds__(256, 2) void gemm_weff() {
    extern __shared__ char smem[];
    uint32_t sb = s2u(smem);
    const int tid  = threadIdx.x;
    const int lane = tid & 31;
    const int wid  = tid >> 5;

    const int z  = blockIdx.z;
    const int br = z / 3, t = z - br * 3;
    const int m0 = blockIdx.y * 128;
    const int n0 = blockIdx.x * 128;
    const __half* Ap = g_w3h + (size_t)z  * 262144 + (size_t)m0 * 512;
    const __half* Bp = g_w1t + (size_t)br * 262144 + (size_t)n0 * 512;

    const int NK = 512 >> 5;   // 16

    auto load_chunk = [&](int kc) {
        uint32_t base = sb + (uint32_t)(kc % 3) * BUF1;
        int ko = kc << 5;
        #pragma unroll
        for (int it = 0; it < 2; it++) {
            int u = tid + it * 256;
            int r = u >> 2, cu = u & 3;
            uint32_t off = (uint32_t)r * ROWB + (uint32_t)cu * 16u;
            cpa16(base + off,        Ap + (size_t)r * 512 + ko + cu * 8);
            cpa16(base + MATB + off, Bp + (size_t)r * 512 + ko + cu * 8);
        }
        cp_commit();
    };

    float acc[2][8][4];
    #pragma unroll
    for (int i = 0; i < 2; i++)
        #pragma unroll
        for (int j = 0; j < 8; j++)
            #pragma unroll
            for (int q = 0; q < 4; q++) acc[i][j][q] = 0.f;

    const int m0w = (wid >> 1) * 32;
    const int n0w = (wid & 1) * 64;
    const int l16 = lane & 15, hi = lane >> 4;

    load_chunk(0);
    load_chunk(1);
    for (int kc = 0; kc < NK; kc++) {
        if (kc + 1 < NK) cp_wait1(); else cp_wait0();
        __syncthreads();
        if (kc + 2 < NK) load_chunk(kc + 2);
        uint32_t base = sb + (uint32_t)(kc % 3) * BUF1;
        uint32_t aAddr = base + (uint32_t)(m0w + l16) * ROWB + (uint32_t)hi * 16u;
        uint32_t bAddr = base + MATB + (uint32_t)(n0w + l16) * ROWB + (uint32_t)hi * 16u;
        #pragma unroll
        for (int ks = 0; ks < 2; ks++) {
            uint32_t koff = (uint32_t)ks * 32u;
            uint32_t av[2][4], bv[4][4];
            ldsm4(av[0][0], av[0][1], av[0][2], av[0][3], aAddr + koff);
            ldsm4(av[1][0], av[1][1], av[1][2], av[1][3], aAddr + 16*ROWB + koff);
            #pragma unroll
            for (int nt = 0; nt < 4; nt++)
                ldsm4(bv[nt][0], bv[nt][1], bv[nt][2], bv[nt][3], bAddr + (uint32_t)nt*16*ROWB + koff);
            #pragma unroll
            for (int mi = 0; mi < 2; mi++) {
                #pragma unroll
                for (int nj = 0; nj < 8; nj++) {
                    int nt = nj >> 1, sel = nj & 1;
                    uint32_t b0 = sel ? bv[nt][1] : bv[nt][0];
                    uint32_t b1 = sel ? bv[nt][3] : bv[nt][2];
                    mma16816(acc[mi][nj], av[mi], b0, b1);
                }
            }
        }
    }

    const int rowBase = m0 + m0w + (lane >> 2);
    const int colBase = n0 + n0w + (lane & 3) * 2;
    #pragma unroll
    for (int mi = 0; mi < 2; mi++) {
        #pragma unroll
        for (int nj = 0; nj < 8; nj++) {
            int c = colBase + nj * 8;
            #pragma unroll
            for (int half = 0; half < 2; half++) {
                int r = rowBase + mi * 16 + half * 8;
                *(__half2*)(g_wh + (size_t)(br*512 + r) * K3 + t*512 + c) =
                    __halves2half2(__float2half_rn(acc[mi][nj][half*2]),
                                   __float2half_rn(acc[mi][nj][half*2+1]));
            }
        }
    }
}

// =====================================================================
// prep_all: one launch for all converts.
// =====================================================================
#define PB_WPROJ 1024
#define PB_X     32768
#define PB_W1T   768
#define PB_W3    9216

__global__ __launch_bounds__(256) void prep_all(const float* __restrict__ x,
                                                const float* __restrict__ wproj,
                                                const float* __restrict__ w1q,
                                                const float* __restrict__ w1k,
                                                const float* __restrict__ w1v,
                                                const float* __restrict__ w3q,
                                                const float* __restrict__ w3k,
                                                const float* __restrict__ w3v) {
    int blk = blockIdx.x;
    int tid = threadIdx.x;
    if (blk < PB_WPROJ) {
        size_t i = (size_t)blk * 256 + tid;
        g_wph[i] = __float2half_rn(wproj[i]);
        return;
    }
    blk -= PB_WPROJ;
    if (blk < PB_X) {
        size_t i = (size_t)blk * 256 + tid;
        float2 v = *(const float2*)(x + i * 2);
        *(__half2*)(g_xh + i * 2) = __halves2half2(__float2half_rn(v.x), __float2half_rn(v.y));
        return;
    }
    blk -= PB_X;
    if (blk < PB_W1T) {
        __shared__ __half tile[32][33];
        int br = blk >> 8;
        int tb = blk & 255;
        int i0 = (tb >> 4) * 32;
        int c0 = (tb & 15) * 32;
        const float* w1 = br == 0 ? w1q : br == 1 ? w1k : w1v;
        int tx = tid & 31, ty = tid >> 5;
        #pragma unroll
        for (int j = 0; j < 32; j += 8)
            tile[ty + j][tx] = __float2half_rn(w1[(size_t)(i0 + ty + j) * 512 + c0 + tx]);
        __syncthreads();
        __half* o = g_w1t + (size_t)br * 262144;
        #pragma unroll
        for (int j = 0; j < 32; j += 8)
            o[(size_t)(c0 + ty + j) * 512 + i0 + tx] = tile[tx][ty + j];
        return;
    }
    blk -= PB_W1T;
    {
        size_t gi = (size_t)blk * 256 + tid;
        int z  = (int)(gi >> 18);
        int oi = (int)(gi & 262143);
        int br = z / 3, t = z - br * 3;
        const float* w3 = br == 0 ? w3q : br == 1 ? w3k : w3v;
        int o = oi >> 9, i = oi & 511;
        g_w3h[gi] = __float2half_rn(w3[(size_t)o * 1536 + i * 3 + t]);
    }
}

// ---------------- launch ----------------
static void* sym(const void* s) { void* p = nullptr; cudaGetSymbolAddress(&p, s); return p; }

extern "C" void kernel_launch(void* const* d_in, const int* in_sizes, int n_in,
                              void* d_out, int out_size) {
    const float* x     = (const float*)d_in[0];
    const float* w1q   = (const float*)d_in[1];
    const float* w3q   = (const float*)d_in[2];
    const float* w1k   = (const float*)d_in[3];
    const float* w3k   = (const float*)d_in[4];
    const float* w1v   = (const float*)d_in[5];
    const float* w3v   = (const float*)d_in[6];
    const float* wproj = (const float*)d_in[7];
    const float* bproj = (const float*)d_in[8];
    float* y = (float*)d_out;

    cudaFuncSetAttribute(gemm_qkv,       cudaFuncAttributeMaxDynamicSharedMemorySize, Q_SMEM);
    cudaFuncSetAttribute(scores_softmax, cudaFuncAttributeMaxDynamicSharedMemorySize, SS_SMEM);
    cudaFuncSetAttribute(gemm1,          cudaFuncAttributeMaxDynamicSharedMemorySize, G1_SMEM);
    cudaFuncSetAttribute(gemm_weff,      cudaFuncAttributeMaxDynamicSharedMemorySize, G1_SMEM);

    __half* vt  = (__half*)sym(g_vt);
    __half* pp  = (__half*)sym(g_p);
    __half* ot  = (__half*)sym(g_ot);
    __half* wph = (__half*)sym(g_wph);

    // prep + weff
    prep_all<<<PB_WPROJ + PB_X + PB_W1T + PB_W3, 256>>>(x, wproj, w1q, w1k, w1v, w3q, w3k, w3v);
    gemm_weff<<<dim3(4, 4, 9), 256, G1_SMEM>>>();

    // QKV (N=128 tiles, 3072 CTAs): q,k -> g_qkv; v -> g_vt transposed
    gemm_qkv<<<dim3(Nn/128, K3/128, Bb), 256, Q_SMEM>>>();

    // scores + softmax fused -> P fp16
    scores_softmax<<<dim3(Cc/64, Bb), 512, SS_SMEM>>>();

    // PV: Ot[n,c] = sum_d vt[n,d] * P[c,d]
    {
        G1Args a = {};
        a.A = vt; a.B = pp;
        a.sA = (long long)Nn * Cc; a.sB = (long long)Cc * Cc; a.sC = (long long)Nn * Cc;
        a.lda = Cc; a.ldb = Cc; a.ldc = Cc; a.K = Cc;
        a.Cf = nullptr; a.Ch = ot; a.bias = nullptr; a.scale = 1.f;
        gemm1<<<dim3(Cc/128, Nn/128, Bb), 256, G1_SMEM>>>(a);
    }

    // proj: y[n,o] = sum_c Ot[n,c] * wproj[o,c] + bias[o]
    {
        G1Args a = {};
        a.A = ot; a.B = wph;
        a.sA = (long long)Nn * Cc; a.sB = 0; a.sC = (long long)Nn * Cc;
        a.lda = Cc; a.ldb = Cc; a.ldc = Cc; a.K = Cc;
        a.Cf = y; a.Ch = nullptr; a.bias = bproj; a.scale = 1.f;
        gemm1<<<dim3(Cc/128, Nn/128, Bb), 256, G1_SMEM>>>(a);
    }
}

// round 16
// speedup vs baseline: 1.0797x; 1.0797x over previous
#include <cuda_runtime.h>
#include <cuda_fp16.h>
#include <cstdint>

#define Bb 16
#define Nn 2048
#define Cc 512
#define K3 1536

// ---------------- device scratch ----------------
__device__ __half g_wh  [1536*1536];   // fp16 Weff [br*512+o][t*512+c]
__device__ __half g_w3h [9*512*512];   // fp16 w3 slices [br*3+t][o][i]
__device__ __half g_w1t [3*512*512];   // fp16 w1 transposed [br][c][i]
__device__ __half g_wph [512*512];     // fp16 wproj
__device__ __half g_xh  [16777216];    // [b][n][c] fp16 x
__device__ __half g_qkv [50331648];    // [b][3C][N] (q,k rows used)
__device__ __half g_vt  [16777216];    // [b][n][d]
__device__ __half g_p   [4194304];     // softmax(S) fp16 [b][c][d]
__device__ __half g_ot  [16777216];    // [b][n][c]

// ---------------- PTX helpers ----------------
__device__ __forceinline__ uint32_t s2u(const void* p){
    uint32_t a; asm("{ .reg .u64 t; cvta.to.shared.u64 t, %1; cvt.u32.u64 %0, t; }" : "=r"(a) : "l"(p)); return a;
}
__device__ __forceinline__ void cpa16(uint32_t d, const void* s){
    asm volatile("cp.async.cg.shared.global [%0], [%1], 16;" :: "r"(d), "l"(s));
}
__device__ __forceinline__ void cp_commit(){ asm volatile("cp.async.commit_group;"); }
__device__ __forceinline__ void cp_wait1(){ asm volatile("cp.async.wait_group 1;"); }
__device__ __forceinline__ void cp_wait0(){ asm volatile("cp.async.wait_group 0;"); }
__device__ __forceinline__ void ldsm4(uint32_t& r0, uint32_t& r1, uint32_t& r2, uint32_t& r3, uint32_t a){
    asm volatile("ldmatrix.sync.aligned.m8n8.x4.shared.b16 {%0,%1,%2,%3}, [%4];"
        : "=r"(r0), "=r"(r1), "=r"(r2), "=r"(r3) : "r"(a));
}
__device__ __forceinline__ void mma16816(float* d, const uint32_t* a, uint32_t b0, uint32_t b1){
    asm volatile("mma.sync.aligned.m16n8k16.row.col.f32.f16.f16.f32 "
        "{%0,%1,%2,%3}, {%4,%5,%6,%7}, {%8,%9}, {%0,%1,%2,%3};"
        : "+f"(d[0]), "+f"(d[1]), "+f"(d[2]), "+f"(d[3])
        : "r"(a[0]), "r"(a[1]), "r"(a[2]), "r"(a[3]), "r"(b0), "r"(b1));
}

#define ROWB 80u
#define MATB 10240u

// =====================================================================
// gemm_qkv (r14/r8 config — best measured). x-dedup, CTA M=128 x N=256,
// 256 thr, warp 32x128 (4Mx2N), 3-stage pipeline. v-row CTAs (by>=8)
// write transposed into g_vt via smem staging.
// =====================================================================
#define QA_OFF  0u
#define QB_OFF  30720u
#define QBUF    51360u
#define Q_SMEM  (3*51360)
#define TR_STRIDE 258

__global__ __launch_bounds__(256, 1) void gemm_qkv() {
    extern __shared__ char smem[];
    uint32_t sb = s2u(smem);
    const int tid  = threadIdx.x;
    const int lane = tid & 31;
    const int wid  = tid >> 5;

    const int b  = blockIdx.z;
    const int m0 = blockIdx.y * 128;
    const int n0 = blockIdx.x * 256;
    const __half* Ap = g_wh + (size_t)m0 * K3;
    const __half* Xb = g_xh + (size_t)b * Nn * Cc;

    const int NK = Cc >> 5;   // 16

    auto load_chunk = [&](int kc) {
        uint32_t base = sb + (uint32_t)(kc % 3) * QBUF;
        int c0 = kc << 5;
        #pragma unroll
        for (int it = 0; it < 6; it++) {
            int u  = tid + it * 256;
            int sl = u >> 9;
            int rm = u & 511;
            int r  = rm >> 2, cu = rm & 3;
            cpa16(base + QA_OFF + (uint32_t)sl*MATB + (uint32_t)r*ROWB + (uint32_t)cu*16u,
                  Ap + (size_t)r * K3 + sl*512 + c0 + cu*8);
        }
        #pragma unroll
        for (int it = 0; it < 4; it++) {
            int u = tid + it * 256;
            int r = u >> 2, cu = u & 3;
            int n = n0 + r - 1;
            if (n < 0) n += Nn; else if (n >= Nn) n -= Nn;
            cpa16(base + QB_OFF + (uint32_t)r*ROWB + (uint32_t)cu*16u,
                  Xb + (size_t)n * Cc + c0 + cu*8);
        }
        if (tid < 8) {
            int u = 1024 + tid;
            int r = u >> 2, cu = u & 3;
            int n = n0 + r - 1;
            if (n >= Nn) n -= Nn;
            cpa16(base + QB_OFF + (uint32_t)r*ROWB + (uint32_t)cu*16u,
                  Xb + (size_t)n * Cc + c0 + cu*8);
        }
        cp_commit();
    };

    float acc[2][16][4];
    #pragma unroll
    for (int i = 0; i < 2; i++)
        #pragma unroll
        for (int j = 0; j < 16; j++)
            #pragma unroll
            for (int q = 0; q < 4; q++) acc[i][j][q] = 0.f;

    const int m0w = (wid >> 1) * 32;
    const int n0w = (wid & 1) * 128;
    const int l16 = lane & 15, hi = lane >> 4;

    load_chunk(0);
    load_chunk(1);
    for (int kc = 0; kc < NK; kc++) {
        if (kc + 1 < NK) cp_wait1(); else cp_wait0();
        __syncthreads();
        if (kc + 2 < NK) load_chunk(kc + 2);
        uint32_t base = sb + (uint32_t)(kc % 3) * QBUF;
        #pragma unroll
        for (int t = 0; t < 3; t++) {
            uint32_t aB = base + QA_OFF + (uint32_t)t*MATB + (uint32_t)(m0w + l16)*ROWB + (uint32_t)hi*16u;
            uint32_t bB = base + QB_OFF + (uint32_t)(n0w + l16 + t)*ROWB + (uint32_t)hi*16u;
            #pragma unroll
            for (int ks = 0; ks < 2; ks++) {
                uint32_t koff = (uint32_t)ks * 32u;
                uint32_t av[2][4], bv[8][4];
                ldsm4(av[0][0], av[0][1], av[0][2], av[0][3], aB + koff);
                ldsm4(av[1][0], av[1][1], av[1][2], av[1][3], aB + 16*ROWB + koff);
                #pragma unroll
                for (int nt = 0; nt < 8; nt++)
                    ldsm4(bv[nt][0], bv[nt][1], bv[nt][2], bv[nt][3],
                          bB + (uint32_t)nt*16*ROWB + koff);
                #pragma unroll
                for (int mi = 0; mi < 2; mi++) {
                    #pragma unroll
                    for (int nj = 0; nj < 16; nj++) {
                        int nt = nj >> 1, sel = nj & 1;
                        uint32_t b0 = sel ? bv[nt][1] : bv[nt][0];
                        uint32_t b1 = sel ? bv[nt][3] : bv[nt][2];
                        mma16816(acc[mi][nj], av[mi], b0, b1);
                    }
                }
            }
        }
    }

    if (blockIdx.y < 8) {
        const int rowBase = m0 + m0w + (lane >> 2);
        const int colBase = n0 + n0w + (lane & 3) * 2;
        __half* C = g_qkv + (size_t)b * K3 * Nn;
        #pragma unroll
        for (int mi = 0; mi < 2; mi++) {
            #pragma unroll
            for (int nj = 0; nj < 16; nj++) {
                int c = colBase + nj * 8;
                #pragma unroll
                for (int half = 0; half < 2; half++) {
                    int r = rowBase + mi * 16 + half * 8;
                    *(__half2*)(C + (size_t)r * Nn + c) =
                        __halves2half2(__float2half_rn(acc[mi][nj][half*2]),
                                       __float2half_rn(acc[mi][nj][half*2+1]));
                }
            }
        }
    } else {
        __syncthreads();
        __half* sEp = (__half*)smem;
        const int rowL = m0w + (lane >> 2);
        const int colL = n0w + (lane & 3) * 2;
        #pragma unroll
        for (int mi = 0; mi < 2; mi++) {
            #pragma unroll
            for (int nj = 0; nj < 16; nj++) {
                int c = colL + nj * 8;
                #pragma unroll
                for (int half = 0; half < 2; half++) {
                    int r = rowL + mi * 16 + half * 8;
                    *(__half2*)(sEp + (size_t)r * TR_STRIDE + c) =
                        __halves2half2(__float2half_rn(acc[mi][nj][half*2]),
                                       __float2half_rn(acc[mi][nj][half*2+1]));
                }
            }
        }
        __syncthreads();
        const int d0 = m0 - 1024;
        __half* VT = g_vt + (size_t)b * Nn * Cc;
        const int nsub = tid >> 6;
        const int d2   = tid & 63;
        #pragma unroll 4
        for (int it = 0; it < 64; it++) {
            int n = it * 4 + nsub;
            __half h0 = sEp[(size_t)(2*d2)   * TR_STRIDE + n];
            __half h1 = sEp[(size_t)(2*d2+1) * TR_STRIDE + n];
            *(__half2*)(VT + (size_t)(n0 + n) * Cc + d0 + 2*d2) = __halves2half2(h0, h1);
        }
    }
}

// =====================================================================
// scores_softmax (r12 config): fused S=(1/C)q.k^T + softmax -> P fp16.
// CTA 64 x 512, 512 threads (2Mx8N), 3-stage pipeline. Grid 128 CTAs.
// =====================================================================
#define SS_AOFF 0u
#define SS_BOFF 5120u
#define SS_BUF  46080u
#define SS_SMEM (3*46080)

__global__ __launch_bounds__(512, 1) void scores_softmax() {
    extern __shared__ char smem[];
    uint32_t sb = s2u(smem);
    const int tid  = threadIdx.x;
    const int lane = tid & 31;
    const int wid  = tid >> 5;

    const int b  = blockIdx.y;
    const int m0 = blockIdx.x * 64;
    const __half* Ap = g_qkv + (size_t)b * K3 * Nn + (size_t)m0 * Nn;
    const __half* Bp = g_qkv + (size_t)b * K3 * Nn + (size_t)512 * Nn;

    const int NK = Nn >> 5;   // 64

    auto load_chunk = [&](int kc) {
        uint32_t base = sb + (uint32_t)(kc % 3) * SS_BUF;
        int ko = kc << 5;
        #pragma unroll
        for (int it = 0; it < 4; it++) {
            int u = tid + it * 512;
            int r = u >> 2, cu = u & 3;
            cpa16(base + SS_BOFF + (uint32_t)r*ROWB + (uint32_t)cu*16u,
                  Bp + (size_t)r * Nn + ko + cu*8);
        }
        if (tid < 256) {
            int r = tid >> 2, cu = tid & 3;
            cpa16(base + SS_AOFF + (uint32_t)r*ROWB + (uint32_t)cu*16u,
                  Ap + (size_t)r * Nn + ko + cu*8);
        }
        cp_commit();
    };

    float acc[2][8][4];
    #pragma unroll
    for (int i = 0; i < 2; i++)
        #pragma unroll
        for (int j = 0; j < 8; j++)
            #pragma unroll
            for (int q = 0; q < 4; q++) acc[i][j][q] = 0.f;

    const int m0w = (wid >> 3) * 32;
    const int n0w = (wid & 7) * 64;
    const int l16 = lane & 15, hi = lane >> 4;

    load_chunk(0);
    load_chunk(1);
    for (int kc = 0; kc < NK; kc++) {
        if (kc + 1 < NK) cp_wait1(); else cp_wait0();
        __syncthreads();
        if (kc + 2 < NK) load_chunk(kc + 2);
        uint32_t base = sb + (uint32_t)(kc % 3) * SS_BUF;
        uint32_t aAddr = base + SS_AOFF + (uint32_t)(m0w + l16) * ROWB + (uint32_t)hi * 16u;
        uint32_t bAddr = base + SS_BOFF + (uint32_t)(n0w + l16) * ROWB + (uint32_t)hi * 16u;
        #pragma unroll
        for (int ks = 0; ks < 2; ks++) {
            uint32_t koff = (uint32_t)ks * 32u;
            uint32_t av[2][4], bv[4][4];
            ldsm4(av[0][0], av[0][1], av[0][2], av[0][3], aAddr + koff);
            ldsm4(av[1][0], av[1][1], av[1][2], av[1][3], aAddr + 16*ROWB + koff);
            #pragma unroll
            for (int nt = 0; nt < 4; nt++)
                ldsm4(bv[nt][0], bv[nt][1], bv[nt][2], bv[nt][3], bAddr + (uint32_t)nt*16*ROWB + koff);
            #pragma unroll
            for (int mi = 0; mi < 2; mi++) {
                #pragma unroll
                for (int nj = 0; nj < 8; nj++) {
                    int nt = nj >> 1, sel = nj & 1;
                    uint32_t b0 = sel ? bv[nt][1] : bv[nt][0];
                    uint32_t b1 = sel ? bv[nt][3] : bv[nt][2];
                    mma16816(acc[mi][nj], av[mi], b0, b1);
                }
            }
        }
    }

    const float scale = 1.0f / (float)Cc;
    #pragma unroll
    for (int mi = 0; mi < 2; mi++)
        #pragma unroll
        for (int nj = 0; nj < 8; nj++)
            #pragma unroll
            for (int q = 0; q < 4; q++) acc[mi][nj][q] *= scale;

    float rmax[4];
    #pragma unroll
    for (int j = 0; j < 4; j++) {
        int mi = j >> 1, half = j & 1;
        float m = -1e30f;
        #pragma unroll
        for (int nj = 0; nj < 8; nj++) {
            m = fmaxf(m, acc[mi][nj][half*2]);
            m = fmaxf(m, acc[mi][nj][half*2+1]);
        }
        rmax[j] = m;
    }
    #pragma unroll
    for (int j = 0; j < 4; j++) {
        rmax[j] = fmaxf(rmax[j], __shfl_xor_sync(0xffffffffu, rmax[j], 1));
        rmax[j] = fmaxf(rmax[j], __shfl_xor_sync(0xffffffffu, rmax[j], 2));
    }
    __syncthreads();
    float* redm = (float*)smem;
    float* reds = (float*)(smem + 4096);
    if ((lane & 3) == 0) {
        #pragma unroll
        for (int j = 0; j < 4; j++) {
            int row = m0w + (lane >> 2) + (j >> 1) * 16 + (j & 1) * 8;
            redm[row * 8 + (wid & 7)] = rmax[j];
        }
    }
    __syncthreads();
    float rM[4];
    #pragma unroll
    for (int j = 0; j < 4; j++) {
        int row = m0w + (lane >> 2) + (j >> 1) * 16 + (j & 1) * 8;
        float m = redm[row * 8];
        #pragma unroll
        for (int g = 1; g < 8; g++) m = fmaxf(m, redm[row * 8 + g]);
        rM[j] = m;
    }
    float rsum[4] = {0.f, 0.f, 0.f, 0.f};
    #pragma unroll
    for (int mi = 0; mi < 2; mi++) {
        #pragma unroll
        for (int half = 0; half < 2; half++) {
            int j = mi * 2 + half;
            #pragma unroll
            for (int nj = 0; nj < 8; nj++) {
                float e0 = __expf(acc[mi][nj][half*2]   - rM[j]);
                float e1 = __expf(acc[mi][nj][half*2+1] - rM[j]);
                acc[mi][nj][half*2]   = e0;
                acc[mi][nj][half*2+1] = e1;
                rsum[j] += e0 + e1;
            }
        }
    }
    #pragma unroll
    for (int j = 0; j < 4; j++) {
        rsum[j] += __shfl_xor_sync(0xffffffffu, rsum[j], 1);
        rsum[j] += __shfl_xor_sync(0xffffffffu, rsum[j], 2);
    }
    if ((lane & 3) == 0) {
        #pragma unroll
        for (int j = 0; j < 4; j++) {
            int row = m0w + (lane >> 2) + (j >> 1) * 16 + (j & 1) * 8;
            reds[row * 8 + (wid & 7)] = rsum[j];
        }
    }
    __syncthreads();
    float rInv[4];
    #pragma unroll
    for (int j = 0; j < 4; j++) {
        int row = m0w + (lane >> 2) + (j >> 1) * 16 + (j & 1) * 8;
        float s = 0.f;
        #pragma unroll
        for (int g = 0; g < 8; g++) s += reds[row * 8 + g];
        rInv[j] = 1.0f / s;
    }
    __half* P = g_p + (size_t)b * Cc * Cc;
    const int rowBase = m0 + m0w + (lane >> 2);
    const int colBase = n0w + (lane & 3) * 2;
    #pragma unroll
    for (int mi = 0; mi < 2; mi++) {
        #pragma unroll
        for (int nj = 0; nj < 8; nj++) {
            int c = colBase + nj * 8;
            #pragma unroll
            for (int half = 0; half < 2; half++) {
                int j = mi * 2 + half;
                int r = rowBase + mi * 16 + half * 8;
                *(__half2*)(P + (size_t)r * Cc + c) =
                    __halves2half2(__float2half_rn(acc[mi][nj][half*2]   * rInv[j]),
                                   __float2half_rn(acc[mi][nj][half*2+1] * rInv[j]));
            }
        }
    }
}

// =====================================================================
// gemm1: generic plain-fp16 GEMM, 3-stage single-sync, 2 CTAs/SM.
// =====================================================================
#define BUF1 20480u
#define G1_SMEM (3*20480)

struct G1Args {
    const __half* A; const __half* B;
    long long sA, sB, sC;
    int lda, ldb, ldc, K;
    float* Cf; __half* Ch;
    const float* bias;
    float scale;
};

__global__ __launch_bounds__(256, 2) void gemm1(const G1Args g) {
    extern __shared__ char smem[];
    uint32_t sb = s2u(smem);
    const int tid  = threadIdx.x;
    const int lane = tid & 31;
    const int wid  = tid >> 5;

    const int b  = blockIdx.z;
    const int m0 = blockIdx.y * 128;
    const int n0 = blockIdx.x * 128;
    const __half* Ap = g.A + (long long)b * g.sA + (long long)m0 * g.lda;
    const __half* Bp = g.B + (long long)b * g.sB + (long long)n0 * g.ldb;

    const int NK = g.K >> 5;

    auto load_chunk = [&](int kc) {
        uint32_t base = sb + (uint32_t)(kc % 3) * BUF1;
        int ko = kc << 5;
        #pragma unroll
        for (int it = 0; it < 2; it++) {
            int u = tid + it * 256;
            int r = u >> 2, cu = u & 3;
            uint32_t off = (uint32_t)r * ROWB + (uint32_t)cu * 16u;
            cpa16(base + off,        Ap + (size_t)r * g.lda + ko + cu * 8);
            cpa16(base + MATB + off, Bp + (size_t)r * g.ldb + ko + cu * 8);
        }
        cp_commit();
    };

    float acc[2][8][4];
    #pragma unroll
    for (int i = 0; i < 2; i++)
        #pragma unroll
        for (int j = 0; j < 8; j++)
            #pragma unroll
            for (int q = 0; q < 4; q++) acc[i][j][q] = 0.f;

    const int m0w = (wid >> 1) * 32;
    const int n0w = (wid & 1) * 64;
    const int l16 = lane & 15, hi = lane >> 4;

    load_chunk(0);
    load_chunk(1);
    for (int kc = 0; kc < NK; kc++) {
        if (kc + 1 < NK) cp_wait1(); else cp_wait0();
        __syncthreads();
        if (kc + 2 < NK) load_chunk(kc + 2);
        uint32_t base = sb + (uint32_t)(kc % 3) * BUF1;
        uint32_t aAddr = base + (uint32_t)(m0w + l16) * ROWB + (uint32_t)hi * 16u;
        uint32_t bAddr = base + MATB + (uint32_t)(n0w + l16) * ROWB + (uint32_t)hi * 16u;
        #pragma unroll
        for (int ks = 0; ks < 2; ks++) {
            uint32_t koff = (uint32_t)ks * 32u;
            uint32_t av[2][4], bv[4][4];
            ldsm4(av[0][0], av[0][1], av[0][2], av[0][3], aAddr + koff);
            ldsm4(av[1][0], av[1][1], av[1][2], av[1][3], aAddr + 16*ROWB + koff);
            #pragma unroll
            for (int nt = 0; nt < 4; nt++)
                ldsm4(bv[nt][0], bv[nt][1], bv[nt][2], bv[nt][3], bAddr + (uint32_t)nt*16*ROWB + koff);
            #pragma unroll
            for (int mi = 0; mi < 2; mi++) {
                #pragma unroll
                for (int nj = 0; nj < 8; nj++) {
                    int nt = nj >> 1, sel = nj & 1;
                    uint32_t b0 = sel ? bv[nt][1] : bv[nt][0];
                    uint32_t b1 = sel ? bv[nt][3] : bv[nt][2];
                    mma16816(acc[mi][nj], av[mi], b0, b1);
                }
            }
        }
    }

    const int rowBase = m0 + m0w + (lane >> 2);
    const int colBase = n0 + n0w + (lane & 3) * 2;
    if (g.Cf) {
        float* C = g.Cf + (long long)b * g.sC;
        #pragma unroll
        for (int mi = 0; mi < 2; mi++) {
            #pragma unroll
            for (int nj = 0; nj < 8; nj++) {
                int c = colBase + nj * 8;
                #pragma unroll
                for (int half = 0; half < 2; half++) {
                    int r = rowBase + mi * 16 + half * 8;
                    float2 v;
                    v.x = acc[mi][nj][half*2 + 0] * g.scale;
                    v.y = acc[mi][nj][half*2 + 1] * g.scale;
                    if (g.bias) { v.x += g.bias[c]; v.y += g.bias[c + 1]; }
                    *(float2*)(C + (long long)r * g.ldc + c) = v;
                }
            }
        }
    } else {
        __half* C = g.Ch + (long long)b * g.sC;
        #pragma unroll
        for (int mi = 0; mi < 2; mi++) {
            #pragma unroll
            for (int nj = 0; nj < 8; nj++) {
                int c = colBase + nj * 8;
                #pragma unroll
                for (int half = 0; half < 2; half++) {
                    int r = rowBase + mi * 16 + half * 8;
                    *(__half2*)(C + (long long)r * g.ldc + c) =
                        __halves2half2(__float2half_rn(acc[mi][nj][half*2]),
                                       __float2half_rn(acc[mi][nj][half*2+1]));
                }
            }
        }
    }
}

// =====================================================================
// gemm_weff: weff[(br*512+o)][t*512+c] = sum_i w3h[z][o][i] * w1t[br][c][i]
// HMMA, grid (4,4,9) = 144 CTAs, 2/SM, single wave.
// =====================================================================
__global__ __launch_bounds__(256, 2) void gemm_weff() {
    extern __shared__ char smem[];
    uint32_t sb = s2u(smem);
    const int tid  = threadIdx.x;
    const int lane = tid & 31;
    const int wid  = tid >> 5;

    const int z  = blockIdx.z;
    const int br = z / 3, t = z - br * 3;
    const int m0 = blockIdx.y * 128;
    const int n0 = blockIdx.x * 128;
    const __half* Ap = g_w3h + (size_t)z  * 262144 + (size_t)m0 * 512;
    const __half* Bp = g_w1t + (size_t)br * 262144 + (size_t)n0 * 512;

    const int NK = 512 >> 5;   // 16

    auto load_chunk = [&](int kc) {
        uint32_t base = sb + (uint32_t)(kc % 3) * BUF1;
        int ko = kc << 5;
        #pragma unroll
        for (int it = 0; it < 2; it++) {
            int u = tid + it * 256;
            int r = u >> 2, cu = u & 3;
            uint32_t off = (uint32_t)r * ROWB + (uint32_t)cu * 16u;
            cpa16(base + off,        Ap + (size_t)r * 512 + ko + cu * 8);
            cpa16(base + MATB + off, Bp + (size_t)r * 512 + ko + cu * 8);
        }
        cp_commit();
    };

    float acc[2][8][4];
    #pragma unroll
    for (int i = 0; i < 2; i++)
        #pragma unroll
        for (int j = 0; j < 8; j++)
            #pragma unroll
            for (int q = 0; q < 4; q++) acc[i][j][q] = 0.f;

    const int m0w = (wid >> 1) * 32;
    const int n0w = (wid & 1) * 64;
    const int l16 = lane & 15, hi = lane >> 4;

    load_chunk(0);
    load_chunk(1);
    for (int kc = 0; kc < NK; kc++) {
        if (kc + 1 < NK) cp_wait1(); else cp_wait0();
        __syncthreads();
        if (kc + 2 < NK) load_chunk(kc + 2);
        uint32_t base = sb + (uint32_t)(kc % 3) * BUF1;
        uint32_t aAddr = base + (uint32_t)(m0w + l16) * ROWB + (uint32_t)hi * 16u;
        uint32_t bAddr = base + MATB + (uint32_t)(n0w + l16) * ROWB + (uint32_t)hi * 16u;
        #pragma unroll
        for (int ks = 0; ks < 2; ks++) {
            uint32_t koff = (uint32_t)ks * 32u;
            uint32_t av[2][4], bv[4][4];
            ldsm4(av[0][0], av[0][1], av[0][2], av[0][3], aAddr + koff);
            ldsm4(av[1][0], av[1][1], av[1][2], av[1][3], aAddr + 16*ROWB + koff);
            #pragma unroll
            for (int nt = 0; nt < 4; nt++)
                ldsm4(bv[nt][0], bv[nt][1], bv[nt][2], bv[nt][3], bAddr + (uint32_t)nt*16*ROWB + koff);
            #pragma unroll
            for (int mi = 0; mi < 2; mi++) {
                #pragma unroll
                for (int nj = 0; nj < 8; nj++) {
                    int nt = nj >> 1, sel = nj & 1;
                    uint32_t b0 = sel ? bv[nt][1] : bv[nt][0];
                    uint32_t b1 = sel ? bv[nt][3] : bv[nt][2];
                    mma16816(acc[mi][nj], av[mi], b0, b1);
                }
            }
        }
    }

    const int rowBase = m0 + m0w + (lane >> 2);
    const int colBase = n0 + n0w + (lane & 3) * 2;
    #pragma unroll
    for (int mi = 0; mi < 2; mi++) {
        #pragma unroll
        for (int nj = 0; nj < 8; nj++) {
            int c = colBase + nj * 8;
            #pragma unroll
            for (int half = 0; half < 2; half++) {
                int r = rowBase + mi * 16 + half * 8;
                *(__half2*)(g_wh + (size_t)(br*512 + r) * K3 + t*512 + c) =
                    __halves2half2(__float2half_rn(acc[mi][nj][half*2]),
                                   __float2half_rn(acc[mi][nj][half*2+1]));
            }
        }
    }
}

// =====================================================================
// prep_all: one launch for all converts.
// =====================================================================
#define PB_WPROJ 1024
#define PB_X     32768
#define PB_W1T   768
#define PB_W3    9216

__global__ __launch_bounds__(256) void prep_all(const float* __restrict__ x,
                                                const float* __restrict__ wproj,
                                                const float* __restrict__ w1q,
                                                const float* __restrict__ w1k,
                                                const float* __restrict__ w1v,
                                                const float* __restrict__ w3q,
                                                const float* __restrict__ w3k,
                                                const float* __restrict__ w3v) {
    int blk = blockIdx.x;
    int tid = threadIdx.x;
    if (blk < PB_WPROJ) {
        size_t i = (size_t)blk * 256 + tid;
        g_wph[i] = __float2half_rn(wproj[i]);
        return;
    }
    blk -= PB_WPROJ;
    if (blk < PB_X) {
        size_t i = (size_t)blk * 256 + tid;
        float2 v = *(const float2*)(x + i * 2);
        *(__half2*)(g_xh + i * 2) = __halves2half2(__float2half_rn(v.x), __float2half_rn(v.y));
        return;
    }
    blk -= PB_X;
    if (blk < PB_W1T) {
        __shared__ __half tile[32][33];
        int br = blk >> 8;
        int tb = blk & 255;
        int i0 = (tb >> 4) * 32;
        int c0 = (tb & 15) * 32;
        const float* w1 = br == 0 ? w1q : br == 1 ? w1k : w1v;
        int tx = tid & 31, ty = tid >> 5;
        #pragma unroll
        for (int j = 0; j < 32; j += 8)
            tile[ty + j][tx] = __float2half_rn(w1[(size_t)(i0 + ty + j) * 512 + c0 + tx]);
        __syncthreads();
        __half* o = g_w1t + (size_t)br * 262144;
        #pragma unroll
        for (int j = 0; j < 32; j += 8)
            o[(size_t)(c0 + ty + j) * 512 + i0 + tx] = tile[tx][ty + j];
        return;
    }
    blk -= PB_W1T;
    {
        size_t gi = (size_t)blk * 256 + tid;
        int z  = (int)(gi >> 18);
        int oi = (int)(gi & 262143);
        int br = z / 3, t = z - br * 3;
        const float* w3 = br == 0 ? w3q : br == 1 ? w3k : w3v;
        int o = oi >> 9, i = oi & 511;
        g_w3h[gi] = __float2half_rn(w3[(size_t)o * 1536 + i * 3 + t]);
    }
}

// ---------------- launch ----------------
static void* sym(const void* s) { void* p = nullptr; cudaGetSymbolAddress(&p, s); return p; }

extern "C" void kernel_launch(void* const* d_in, const int* in_sizes, int n_in,
                              void* d_out, int out_size) {
    const float* x     = (const float*)d_in[0];
    const float* w1q   = (const float*)d_in[1];
    const float* w3q   = (const float*)d_in[2];
    const float* w1k   = (const float*)d_in[3];
    const float* w3k   = (const float*)d_in[4];
    const float* w1v   = (const float*)d_in[5];
    const float* w3v   = (const float*)d_in[6];
    const float* wproj = (const float*)d_in[7];
    const float* bproj = (const float*)d_in[8];
    float* y = (float*)d_out;

    cudaFuncSetAttribute(gemm_qkv,       cudaFuncAttributeMaxDynamicSharedMemorySize, Q_SMEM);
    cudaFuncSetAttribute(scores_softmax, cudaFuncAttributeMaxDynamicSharedMemorySize, SS_SMEM);
    cudaFuncSetAttribute(gemm1,          cudaFuncAttributeMaxDynamicSharedMemorySize, G1_SMEM);
    cudaFuncSetAttribute(gemm_weff,      cudaFuncAttributeMaxDynamicSharedMemorySize, G1_SMEM);

    __half* vt  = (__half*)sym(g_vt);
    __half* pp  = (__half*)sym(g_p);
    __half* ot  = (__half*)sym(g_ot);
    __half* wph = (__half*)sym(g_wph);

    // prep + weff
    prep_all<<<PB_WPROJ + PB_X + PB_W1T + PB_W3, 256>>>(x, wproj, w1q, w1k, w1v, w3q, w3k, w3v);
    gemm_weff<<<dim3(4, 4, 9), 256, G1_SMEM>>>();

    // QKV (N=256 tiles, 1536 CTAs): q,k -> g_qkv; v -> g_vt transposed
    gemm_qkv<<<dim3(Nn/256, K3/128, Bb), 256, Q_SMEM>>>();

    // scores + softmax fused -> P fp16
    scores_softmax<<<dim3(Cc/64, Bb), 512, SS_SMEM>>>();

    // PV: Ot[n,c] = sum_d vt[n,d] * P[c,d]
    {
        G1Args a = {};
        a.A = vt; a.B = pp;
        a.sA = (long long)Nn * Cc; a.sB = (long long)Cc * Cc; a.sC = (long long)Nn * Cc;
        a.lda = Cc; a.ldb = Cc; a.ldc = Cc; a.K = Cc;
        a.Cf = nullptr; a.Ch = ot; a.bias = nullptr; a.scale = 1.f;
        gemm1<<<dim3(Cc/128, Nn/128, Bb), 256, G1_SMEM>>>(a);
    }

    // proj: y[n,o] = sum_c Ot[n,c] * wproj[o,c] + bias[o]
    {
        G1Args a = {};
        a.A = ot; a.B = wph;
        a.sA = (long long)Nn * Cc; a.sB = 0; a.sC = (long long)Nn * Cc;
        a.lda = Cc; a.ldb = Cc; a.ldc = Cc; a.K = Cc;
        a.Cf = y; a.Ch = nullptr; a.bias = bproj; a.scale = 1.f;
        gemm1<<<dim3(Cc/128, Nn/128, Bb), 256, G1_SMEM>>>(a);
    }
}

// round 17
// speedup vs baseline: 1.0957x; 1.0148x over previous
#include <cuda_runtime.h>
#include <cuda_fp16.h>
#include <cstdint>

#define Bb 16
#define Nn 2048
#define Cc 512
#define K3 1536

// ---------------- device scratch ----------------
__device__ __half g_wh  [1536*1536];   // fp16 Weff [br*512+o][t*512+c]
__device__ __half g_w3h [9*512*512];   // fp16 w3 slices [br*3+t][o][i]
__device__ __half g_w1t [3*512*512];   // fp16 w1 transposed [br][c][i]
__device__ __half g_wph [512*512];     // fp16 wproj
__device__ __half g_xh  [16777216];    // [b][n][c] fp16 x
__device__ __half g_qkv [50331648];    // [b][3C][N] (q,k rows used)
__device__ __half g_vt  [16777216];    // [b][n][d]
__device__ __half g_p   [4194304];     // softmax(S) fp16 [b][c][d]

// ---------------- PTX helpers ----------------
__device__ __forceinline__ uint32_t s2u(const void* p){
    uint32_t a; asm("{ .reg .u64 t; cvta.to.shared.u64 t, %1; cvt.u32.u64 %0, t; }" : "=r"(a) : "l"(p)); return a;
}
__device__ __forceinline__ void cpa16(uint32_t d, const void* s){
    asm volatile("cp.async.cg.shared.global [%0], [%1], 16;" :: "r"(d), "l"(s));
}
__device__ __forceinline__ void cp_commit(){ asm volatile("cp.async.commit_group;"); }
__device__ __forceinline__ void cp_wait1(){ asm volatile("cp.async.wait_group 1;"); }
__device__ __forceinline__ void cp_wait0(){ asm volatile("cp.async.wait_group 0;"); }
__device__ __forceinline__ void ldsm4(uint32_t& r0, uint32_t& r1, uint32_t& r2, uint32_t& r3, uint32_t a){
    asm volatile("ldmatrix.sync.aligned.m8n8.x4.shared.b16 {%0,%1,%2,%3}, [%4];"
        : "=r"(r0), "=r"(r1), "=r"(r2), "=r"(r3) : "r"(a));
}
__device__ __forceinline__ void mma16816(float* d, const uint32_t* a, uint32_t b0, uint32_t b1){
    asm volatile("mma.sync.aligned.m16n8k16.row.col.f32.f16.f16.f32 "
        "{%0,%1,%2,%3}, {%4,%5,%6,%7}, {%8,%9}, {%0,%1,%2,%3};"
        : "+f"(d[0]), "+f"(d[1]), "+f"(d[2]), "+f"(d[3])
        : "r"(a[0]), "r"(a[1]), "r"(a[2]), "r"(a[3]), "r"(b0), "r"(b1));
}

#define ROWB 80u
#define MATB 10240u

// =====================================================================
// gemm_qkv (r14/r8 config — best measured). x-dedup, CTA M=128 x N=256,
// 256 thr, warp 32x128 (4Mx2N), 3-stage pipeline. v-row CTAs (by>=8)
// write transposed into g_vt via smem staging.
// =====================================================================
#define QA_OFF  0u
#define QB_OFF  30720u
#define QBUF    51360u
#define Q_SMEM  (3*51360)
#define TR_STRIDE 258

__global__ __launch_bounds__(256, 1) void gemm_qkv() {
    extern __shared__ char smem[];
    uint32_t sb = s2u(smem);
    const int tid  = threadIdx.x;
    const int lane = tid & 31;
    const int wid  = tid >> 5;

    const int b  = blockIdx.z;
    const int m0 = blockIdx.y * 128;
    const int n0 = blockIdx.x * 256;
    const __half* Ap = g_wh + (size_t)m0 * K3;
    const __half* Xb = g_xh + (size_t)b * Nn * Cc;

    const int NK = Cc >> 5;   // 16

    auto load_chunk = [&](int kc) {
        uint32_t base = sb + (uint32_t)(kc % 3) * QBUF;
        int c0 = kc << 5;
        #pragma unroll
        for (int it = 0; it < 6; it++) {
            int u  = tid + it * 256;
            int sl = u >> 9;
            int rm = u & 511;
            int r  = rm >> 2, cu = rm & 3;
            cpa16(base + QA_OFF + (uint32_t)sl*MATB + (uint32_t)r*ROWB + (uint32_t)cu*16u,
                  Ap + (size_t)r * K3 + sl*512 + c0 + cu*8);
        }
        #pragma unroll
        for (int it = 0; it < 4; it++) {
            int u = tid + it * 256;
            int r = u >> 2, cu = u & 3;
            int n = n0 + r - 1;
            if (n < 0) n += Nn; else if (n >= Nn) n -= Nn;
            cpa16(base + QB_OFF + (uint32_t)r*ROWB + (uint32_t)cu*16u,
                  Xb + (size_t)n * Cc + c0 + cu*8);
        }
        if (tid < 8) {
            int u = 1024 + tid;
            int r = u >> 2, cu = u & 3;
            int n = n0 + r - 1;
            if (n >= Nn) n -= Nn;
            cpa16(base + QB_OFF + (uint32_t)r*ROWB + (uint32_t)cu*16u,
                  Xb + (size_t)n * Cc + c0 + cu*8);
        }
        cp_commit();
    };

    float acc[2][16][4];
    #pragma unroll
    for (int i = 0; i < 2; i++)
        #pragma unroll
        for (int j = 0; j < 16; j++)
            #pragma unroll
            for (int q = 0; q < 4; q++) acc[i][j][q] = 0.f;

    const int m0w = (wid >> 1) * 32;
    const int n0w = (wid & 1) * 128;
    const int l16 = lane & 15, hi = lane >> 4;

    load_chunk(0);
    load_chunk(1);
    for (int kc = 0; kc < NK; kc++) {
        if (kc + 1 < NK) cp_wait1(); else cp_wait0();
        __syncthreads();
        if (kc + 2 < NK) load_chunk(kc + 2);
        uint32_t base = sb + (uint32_t)(kc % 3) * QBUF;
        #pragma unroll
        for (int t = 0; t < 3; t++) {
            uint32_t aB = base + QA_OFF + (uint32_t)t*MATB + (uint32_t)(m0w + l16)*ROWB + (uint32_t)hi*16u;
            uint32_t bB = base + QB_OFF + (uint32_t)(n0w + l16 + t)*ROWB + (uint32_t)hi*16u;
            #pragma unroll
            for (int ks = 0; ks < 2; ks++) {
                uint32_t koff = (uint32_t)ks * 32u;
                uint32_t av[2][4], bv[8][4];
                ldsm4(av[0][0], av[0][1], av[0][2], av[0][3], aB + koff);
                ldsm4(av[1][0], av[1][1], av[1][2], av[1][3], aB + 16*ROWB + koff);
                #pragma unroll
                for (int nt = 0; nt < 8; nt++)
                    ldsm4(bv[nt][0], bv[nt][1], bv[nt][2], bv[nt][3],
                          bB + (uint32_t)nt*16*ROWB + koff);
                #pragma unroll
                for (int mi = 0; mi < 2; mi++) {
                    #pragma unroll
                    for (int nj = 0; nj < 16; nj++) {
                        int nt = nj >> 1, sel = nj & 1;
                        uint32_t b0 = sel ? bv[nt][1] : bv[nt][0];
                        uint32_t b1 = sel ? bv[nt][3] : bv[nt][2];
                        mma16816(acc[mi][nj], av[mi], b0, b1);
                    }
                }
            }
        }
    }

    if (blockIdx.y < 8) {
        const int rowBase = m0 + m0w + (lane >> 2);
        const int colBase = n0 + n0w + (lane & 3) * 2;
        __half* C = g_qkv + (size_t)b * K3 * Nn;
        #pragma unroll
        for (int mi = 0; mi < 2; mi++) {
            #pragma unroll
            for (int nj = 0; nj < 16; nj++) {
                int c = colBase + nj * 8;
                #pragma unroll
                for (int half = 0; half < 2; half++) {
                    int r = rowBase + mi * 16 + half * 8;
                    *(__half2*)(C + (size_t)r * Nn + c) =
                        __halves2half2(__float2half_rn(acc[mi][nj][half*2]),
                                       __float2half_rn(acc[mi][nj][half*2+1]));
                }
            }
        }
    } else {
        __syncthreads();
        __half* sEp = (__half*)smem;
        const int rowL = m0w + (lane >> 2);
        const int colL = n0w + (lane & 3) * 2;
        #pragma unroll
        for (int mi = 0; mi < 2; mi++) {
            #pragma unroll
            for (int nj = 0; nj < 16; nj++) {
                int c = colL + nj * 8;
                #pragma unroll
                for (int half = 0; half < 2; half++) {
                    int r = rowL + mi * 16 + half * 8;
                    *(__half2*)(sEp + (size_t)r * TR_STRIDE + c) =
                        __halves2half2(__float2half_rn(acc[mi][nj][half*2]),
                                       __float2half_rn(acc[mi][nj][half*2+1]));
                }
            }
        }
        __syncthreads();
        const int d0 = m0 - 1024;
        __half* VT = g_vt + (size_t)b * Nn * Cc;
        const int nsub = tid >> 6;
        const int d2   = tid & 63;
        #pragma unroll 4
        for (int it = 0; it < 64; it++) {
            int n = it * 4 + nsub;
            __half h0 = sEp[(size_t)(2*d2)   * TR_STRIDE + n];
            __half h1 = sEp[(size_t)(2*d2+1) * TR_STRIDE + n];
            *(__half2*)(VT + (size_t)(n0 + n) * Cc + d0 + 2*d2) = __halves2half2(h0, h1);
        }
    }
}

// =====================================================================
// scores_softmax (r12 config): fused S=(1/C)q.k^T + softmax -> P fp16.
// CTA 64 x 512, 512 threads (2Mx8N), 3-stage pipeline. Grid 128 CTAs.
// =====================================================================
#define SS_AOFF 0u
#define SS_BOFF 5120u
#define SS_BUF  46080u
#define SS_SMEM (3*46080)

__global__ __launch_bounds__(512, 1) void scores_softmax() {
    extern __shared__ char smem[];
    uint32_t sb = s2u(smem);
    const int tid  = threadIdx.x;
    const int lane = tid & 31;
    const int wid  = tid >> 5;

    const int b  = blockIdx.y;
    const int m0 = blockIdx.x * 64;
    const __half* Ap = g_qkv + (size_t)b * K3 * Nn + (size_t)m0 * Nn;
    const __half* Bp = g_qkv + (size_t)b * K3 * Nn + (size_t)512 * Nn;

    const int NK = Nn >> 5;   // 64

    auto load_chunk = [&](int kc) {
        uint32_t base = sb + (uint32_t)(kc % 3) * SS_BUF;
        int ko = kc << 5;
        #pragma unroll
        for (int it = 0; it < 4; it++) {
            int u = tid + it * 512;
            int r = u >> 2, cu = u & 3;
            cpa16(base + SS_BOFF + (uint32_t)r*ROWB + (uint32_t)cu*16u,
                  Bp + (size_t)r * Nn + ko + cu*8);
        }
        if (tid < 256) {
            int r = tid >> 2, cu = tid & 3;
            cpa16(base + SS_AOFF + (uint32_t)r*ROWB + (uint32_t)cu*16u,
                  Ap + (size_t)r * Nn + ko + cu*8);
        }
        cp_commit();
    };

    float acc[2][8][4];
    #pragma unroll
    for (int i = 0; i < 2; i++)
        #pragma unroll
        for (int j = 0; j < 8; j++)
            #pragma unroll
            for (int q = 0; q < 4; q++) acc[i][j][q] = 0.f;

    const int m0w = (wid >> 3) * 32;
    const int n0w = (wid & 7) * 64;
    const int l16 = lane & 15, hi = lane >> 4;

    load_chunk(0);
    load_chunk(1);
    for (int kc = 0; kc < NK; kc++) {
        if (kc + 1 < NK) cp_wait1(); else cp_wait0();
        __syncthreads();
        if (kc + 2 < NK) load_chunk(kc + 2);
        uint32_t base = sb + (uint32_t)(kc % 3) * SS_BUF;
        uint32_t aAddr = base + SS_AOFF + (uint32_t)(m0w + l16) * ROWB + (uint32_t)hi * 16u;
        uint32_t bAddr = base + SS_BOFF + (uint32_t)(n0w + l16) * ROWB + (uint32_t)hi * 16u;
        #pragma unroll
        for (int ks = 0; ks < 2; ks++) {
            uint32_t koff = (uint32_t)ks * 32u;
            uint32_t av[2][4], bv[4][4];
            ldsm4(av[0][0], av[0][1], av[0][2], av[0][3], aAddr + koff);
            ldsm4(av[1][0], av[1][1], av[1][2], av[1][3], aAddr + 16*ROWB + koff);
            #pragma unroll
            for (int nt = 0; nt < 4; nt++)
                ldsm4(bv[nt][0], bv[nt][1], bv[nt][2], bv[nt][3], bAddr + (uint32_t)nt*16*ROWB + koff);
            #pragma unroll
            for (int mi = 0; mi < 2; mi++) {
                #pragma unroll
                for (int nj = 0; nj < 8; nj++) {
                    int nt = nj >> 1, sel = nj & 1;
                    uint32_t b0 = sel ? bv[nt][1] : bv[nt][0];
                    uint32_t b1 = sel ? bv[nt][3] : bv[nt][2];
                    mma16816(acc[mi][nj], av[mi], b0, b1);
                }
            }
        }
    }

    const float scale = 1.0f / (float)Cc;
    #pragma unroll
    for (int mi = 0; mi < 2; mi++)
        #pragma unroll
        for (int nj = 0; nj < 8; nj++)
            #pragma unroll
            for (int q = 0; q < 4; q++) acc[mi][nj][q] *= scale;

    float rmax[4];
    #pragma unroll
    for (int j = 0; j < 4; j++) {
        int mi = j >> 1, half = j & 1;
        float m = -1e30f;
        #pragma unroll
        for (int nj = 0; nj < 8; nj++) {
            m = fmaxf(m, acc[mi][nj][half*2]);
            m = fmaxf(m, acc[mi][nj][half*2+1]);
        }
        rmax[j] = m;
    }
    #pragma unroll
    for (int j = 0; j < 4; j++) {
        rmax[j] = fmaxf(rmax[j], __shfl_xor_sync(0xffffffffu, rmax[j], 1));
        rmax[j] = fmaxf(rmax[j], __shfl_xor_sync(0xffffffffu, rmax[j], 2));
    }
    __syncthreads();
    float* redm = (float*)smem;
    float* reds = (float*)(smem + 4096);
    if ((lane & 3) == 0) {
        #pragma unroll
        for (int j = 0; j < 4; j++) {
            int row = m0w + (lane >> 2) + (j >> 1) * 16 + (j & 1) * 8;
            redm[row * 8 + (wid & 7)] = rmax[j];
        }
    }
    __syncthreads();
    float rM[4];
    #pragma unroll
    for (int j = 0; j < 4; j++) {
        int row = m0w + (lane >> 2) + (j >> 1) * 16 + (j & 1) * 8;
        float m = redm[row * 8];
        #pragma unroll
        for (int g = 1; g < 8; g++) m = fmaxf(m, redm[row * 8 + g]);
        rM[j] = m;
    }
    float rsum[4] = {0.f, 0.f, 0.f, 0.f};
    #pragma unroll
    for (int mi = 0; mi < 2; mi++) {
        #pragma unroll
        for (int half = 0; half < 2; half++) {
            int j = mi * 2 + half;
            #pragma unroll
            for (int nj = 0; nj < 8; nj++) {
                float e0 = __expf(acc[mi][nj][half*2]   - rM[j]);
                float e1 = __expf(acc[mi][nj][half*2+1] - rM[j]);
                acc[mi][nj][half*2]   = e0;
                acc[mi][nj][half*2+1] = e1;
                rsum[j] += e0 + e1;
            }
        }
    }
    #pragma unroll
    for (int j = 0; j < 4; j++) {
        rsum[j] += __shfl_xor_sync(0xffffffffu, rsum[j], 1);
        rsum[j] += __shfl_xor_sync(0xffffffffu, rsum[j], 2);
    }
    if ((lane & 3) == 0) {
        #pragma unroll
        for (int j = 0; j < 4; j++) {
            int row = m0w + (lane >> 2) + (j >> 1) * 16 + (j & 1) * 8;
            reds[row * 8 + (wid & 7)] = rsum[j];
        }
    }
    __syncthreads();
    float rInv[4];
    #pragma unroll
    for (int j = 0; j < 4; j++) {
        int row = m0w + (lane >> 2) + (j >> 1) * 16 + (j & 1) * 8;
        float s = 0.f;
        #pragma unroll
        for (int g = 0; g < 8; g++) s += reds[row * 8 + g];
        rInv[j] = 1.0f / s;
    }
    __half* P = g_p + (size_t)b * Cc * Cc;
    const int rowBase = m0 + m0w + (lane >> 2);
    const int colBase = n0w + (lane & 3) * 2;
    #pragma unroll
    for (int mi = 0; mi < 2; mi++) {
        #pragma unroll
        for (int nj = 0; nj < 8; nj++) {
            int c = colBase + nj * 8;
            #pragma unroll
            for (int half = 0; half < 2; half++) {
                int j = mi * 2 + half;
                int r = rowBase + mi * 16 + half * 8;
                *(__half2*)(P + (size_t)r * Cc + c) =
                    __halves2half2(__float2half_rn(acc[mi][nj][half*2]   * rInv[j]),
                                   __float2half_rn(acc[mi][nj][half*2+1] * rInv[j]));
            }
        }
    }
}

// =====================================================================
// pv_proj: fused PV + projection. CTA owns 128 n-rows of one batch.
// Phase 1: Ot[128 x 512] = vt[n-rows] . P^T, staged in smem chunked
//          layout (16 chunks x [128 rows x 80B]).
// Phase 2: y[n][o] = Ot . wproj^T + bias, A read from resident smem.
// 256 threads, warps 4Mx2N, grid (Nn/128, Bb) = 256 CTAs, 1/SM.
// =====================================================================
#define BUF1 20480u
#define PP_OT   61440u                      // Ot region after 3-stage pipeline
#define PP_SMEM (61440 + 16*10240)          // 225280 B

__global__ __launch_bounds__(256, 1) void pv_proj(const float* __restrict__ bias,
                                                  float* __restrict__ y) {
    extern __shared__ char smem[];
    uint32_t sb = s2u(smem);
    const int tid  = threadIdx.x;
    const int lane = tid & 31;
    const int wid  = tid >> 5;

    const int b  = blockIdx.y;
    const int n0 = blockIdx.x * 128;
    const __half* VT = g_vt + (size_t)b * Nn * Cc + (size_t)n0 * Cc;
    const __half* P  = g_p  + (size_t)b * Cc * Cc;

    const int m0w = (wid >> 1) * 32;
    const int n0w = (wid & 1) * 64;
    const int l16 = lane & 15, hi = lane >> 4;

    // ---------------- Phase 1: Ot = vt . P^T (4 column passes) --------
    for (int cc = 0; cc < 4; cc++) {
        const __half* Bp = P + (size_t)(cc * 128) * Cc;

        auto load_chunk = [&](int kc) {
            uint32_t base = sb + (uint32_t)(kc % 3) * BUF1;
            int ko = kc << 5;
            #pragma unroll
            for (int it = 0; it < 2; it++) {
                int u = tid + it * 256;
                int r = u >> 2, cu = u & 3;
                uint32_t off = (uint32_t)r * ROWB + (uint32_t)cu * 16u;
                cpa16(base + off,        VT + (size_t)r * Cc + ko + cu * 8);
                cpa16(base + MATB + off, Bp + (size_t)r * Cc + ko + cu * 8);
            }
            cp_commit();
        };

        float acc[2][8][4];
        #pragma unroll
        for (int i = 0; i < 2; i++)
            #pragma unroll
            for (int j = 0; j < 8; j++)
                #pragma unroll
                for (int q = 0; q < 4; q++) acc[i][j][q] = 0.f;

        __syncthreads();                 // stage buffers free before reuse
        load_chunk(0);
        load_chunk(1);
        for (int kc = 0; kc < 16; kc++) {
            if (kc + 1 < 16) cp_wait1(); else cp_wait0();
            __syncthreads();
            if (kc + 2 < 16) load_chunk(kc + 2);
            uint32_t base = sb + (uint32_t)(kc % 3) * BUF1;
            uint32_t aAddr = base + (uint32_t)(m0w + l16) * ROWB + (uint32_t)hi * 16u;
            uint32_t bAddr = base + MATB + (uint32_t)(n0w + l16) * ROWB + (uint32_t)hi * 16u;
            #pragma unroll
            for (int ks = 0; ks < 2; ks++) {
                uint32_t koff = (uint32_t)ks * 32u;
                uint32_t av[2][4], bv[4][4];
                ldsm4(av[0][0], av[0][1], av[0][2], av[0][3], aAddr + koff);
                ldsm4(av[1][0], av[1][1], av[1][2], av[1][3], aAddr + 16*ROWB + koff);
                #pragma unroll
                for (int nt = 0; nt < 4; nt++)
                    ldsm4(bv[nt][0], bv[nt][1], bv[nt][2], bv[nt][3], bAddr + (uint32_t)nt*16*ROWB + koff);
                #pragma unroll
                for (int mi = 0; mi < 2; mi++) {
                    #pragma unroll
                    for (int nj = 0; nj < 8; nj++) {
                        int nt = nj >> 1, sel = nj & 1;
                        uint32_t b0 = sel ? bv[nt][1] : bv[nt][0];
                        uint32_t b1 = sel ? bv[nt][3] : bv[nt][2];
                        mma16816(acc[mi][nj], av[mi], b0, b1);
                    }
                }
            }
        }

        // epilogue: write fp16 Ot into chunked smem layout
        const int rowL = m0w + (lane >> 2);
        const int colL = cc * 128 + n0w + (lane & 3) * 2;
        #pragma unroll
        for (int mi = 0; mi < 2; mi++) {
            #pragma unroll
            for (int nj = 0; nj < 8; nj++) {
                int c = colL + nj * 8;
                int chunk = c >> 5, cw = c & 31;
                #pragma unroll
                for (int half = 0; half < 2; half++) {
                    int r = rowL + mi * 16 + half * 8;
                    *(__half2*)(smem + PP_OT + (size_t)chunk * MATB + (size_t)r * ROWB + cw * 2) =
                        __halves2half2(__float2half_rn(acc[mi][nj][half*2]),
                                       __float2half_rn(acc[mi][nj][half*2+1]));
                }
            }
        }
    }
    __syncthreads();                     // Ot fully staged; stage buffers free

    // ---------------- Phase 2: y = Ot . wproj^T + bias (4 output passes)
    for (int oo = 0; oo < 4; oo++) {
        const __half* Bp = g_wph + (size_t)(oo * 128) * Cc;

        auto loadB = [&](int kc) {
            uint32_t base = sb + (uint32_t)(kc % 3) * MATB;
            int ko = kc << 5;
            #pragma unroll
            for (int it = 0; it < 2; it++) {
                int u = tid + it * 256;
                int r = u >> 2, cu = u & 3;
                cpa16(base + (uint32_t)r * ROWB + (uint32_t)cu * 16u,
                      Bp + (size_t)r * Cc + ko + cu * 8);
            }
            cp_commit();
        };

        float acc[2][8][4];
        #pragma unroll
        for (int i = 0; i < 2; i++)
            #pragma unroll
            for (int j = 0; j < 8; j++)
                #pragma unroll
                for (int q = 0; q < 4; q++) acc[i][j][q] = 0.f;

        if (oo > 0) __syncthreads();     // B stages free before reuse
        loadB(0);
        loadB(1);
        for (int kc = 0; kc < 16; kc++) {
            if (kc + 1 < 16) cp_wait1(); else cp_wait0();
            __syncthreads();
            if (kc + 2 < 16) loadB(kc + 2);
            uint32_t aAddr = sb + PP_OT + (uint32_t)kc * MATB
                           + (uint32_t)(m0w + l16) * ROWB + (uint32_t)hi * 16u;
            uint32_t bAddr = sb + (uint32_t)(kc % 3) * MATB
                           + (uint32_t)(n0w + l16) * ROWB + (uint32_t)hi * 16u;
            #pragma unroll
            for (int ks = 0; ks < 2; ks++) {
                uint32_t koff = (uint32_t)ks * 32u;
                uint32_t av[2][4], bv[4][4];
                ldsm4(av[0][0], av[0][1], av[0][2], av[0][3], aAddr + koff);
                ldsm4(av[1][0], av[1][1], av[1][2], av[1][3], aAddr + 16*ROWB + koff);
                #pragma unroll
                for (int nt = 0; nt < 4; nt++)
                    ldsm4(bv[nt][0], bv[nt][1], bv[nt][2], bv[nt][3], bAddr + (uint32_t)nt*16*ROWB + koff);
                #pragma unroll
                for (int mi = 0; mi < 2; mi++) {
                    #pragma unroll
                    for (int nj = 0; nj < 8; nj++) {
                        int nt = nj >> 1, sel = nj & 1;
                        uint32_t b0 = sel ? bv[nt][1] : bv[nt][0];
                        uint32_t b1 = sel ? bv[nt][3] : bv[nt][2];
                        mma16816(acc[mi][nj], av[mi], b0, b1);
                    }
                }
            }
        }

        // epilogue: fp32 y with bias
        const int rowBase = n0 + m0w + (lane >> 2);
        const int colBase = oo * 128 + n0w + (lane & 3) * 2;
        #pragma unroll
        for (int mi = 0; mi < 2; mi++) {
            #pragma unroll
            for (int nj = 0; nj < 8; nj++) {
                int c = colBase + nj * 8;
                #pragma unroll
                for (int half = 0; half < 2; half++) {
                    int r = rowBase + mi * 16 + half * 8;
                    float2 v;
                    v.x = acc[mi][nj][half*2 + 0] + bias[c];
                    v.y = acc[mi][nj][half*2 + 1] + bias[c + 1];
                    *(float2*)(y + ((size_t)b * Nn + r) * Cc + c) = v;
                }
            }
        }
    }
}

// =====================================================================
// gemm_weff: weff[(br*512+o)][t*512+c] = sum_i w3h[z][o][i] * w1t[br][c][i]
// HMMA, grid (4,4,9) = 144 CTAs, 2/SM, single wave.
// =====================================================================
#define G1_SMEM (3*20480)

__global__ __launch_bounds__(256, 2) void gemm_weff() {
    extern __shared__ char smem[];
    uint32_t sb = s2u(smem);
    const int tid  = threadIdx.x;
    const int lane = tid & 31;
    const int wid  = tid >> 5;

    const int z  = blockIdx.z;
    const int br = z / 3, t = z - br * 3;
    const int m0 = blockIdx.y * 128;
    const int n0 = blockIdx.x * 128;
    const __half* Ap = g_w3h + (size_t)z  * 262144 + (size_t)m0 * 512;
    const __half* Bp = g_w1t + (size_t)br * 262144 + (size_t)n0 * 512;

    const int NK = 512 >> 5;   // 16

    auto load_chunk = [&](int kc) {
        uint32_t base = sb + (uint32_t)(kc % 3) * BUF1;
        int ko = kc << 5;
        #pragma unroll
        for (int it = 0; it < 2; it++) {
            int u = tid + it * 256;
            int r = u >> 2, cu = u & 3;
            uint32_t off = (uint32_t)r * ROWB + (uint32_t)cu * 16u;
            cpa16(base + off,        Ap + (size_t)r * 512 + ko + cu * 8);
            cpa16(base + MATB + off, Bp + (size_t)r * 512 + ko + cu * 8);
        }
        cp_commit();
    };

    float acc[2][8][4];
    #pragma unroll
    for (int i = 0; i < 2; i++)
        #pragma unroll
        for (int j = 0; j < 8; j++)
            #pragma unroll
            for (int q = 0; q < 4; q++) acc[i][j][q] = 0.f;

    const int m0w = (wid >> 1) * 32;
    const int n0w = (wid & 1) * 64;
    const int l16 = lane & 15, hi = lane >> 4;

    load_chunk(0);
    load_chunk(1);
    for (int kc = 0; kc < NK; kc++) {
        if (kc + 1 < NK) cp_wait1(); else cp_wait0();
        __syncthreads();
        if (kc + 2 < NK) load_chunk(kc + 2);
        uint32_t base = sb + (uint32_t)(kc % 3) * BUF1;
        uint32_t aAddr = base + (uint32_t)(m0w + l16) * ROWB + (uint32_t)hi * 16u;
        uint32_t bAddr = base + MATB + (uint32_t)(n0w + l16) * ROWB + (uint32_t)hi * 16u;
        #pragma unroll
        for (int ks = 0; ks < 2; ks++) {
            uint32_t koff = (uint32_t)ks * 32u;
            uint32_t av[2][4], bv[4][4];
            ldsm4(av[0][0], av[0][1], av[0][2], av[0][3], aAddr + koff);
            ldsm4(av[1][0], av[1][1], av[1][2], av[1][3], aAddr + 16*ROWB + koff);
            #pragma unroll
            for (int nt = 0; nt < 4; nt++)
                ldsm4(bv[nt][0], bv[nt][1], bv[nt][2], bv[nt][3], bAddr + (uint32_t)nt*16*ROWB + koff);
            #pragma unroll
            for (int mi = 0; mi < 2; mi++) {
                #pragma unroll
                for (int nj = 0; nj < 8; nj++) {
                    int nt = nj >> 1, sel = nj & 1;
                    uint32_t b0 = sel ? bv[nt][1] : bv[nt][0];
                    uint32_t b1 = sel ? bv[nt][3] : bv[nt][2];
                    mma16816(acc[mi][nj], av[mi], b0, b1);
                }
            }
        }
    }

    const int rowBase = m0 + m0w + (lane >> 2);
    const int colBase = n0 + n0w + (lane & 3) * 2;
    #pragma unroll
    for (int mi = 0; mi < 2; mi++) {
        #pragma unroll
        for (int nj = 0; nj < 8; nj++) {
            int c = colBase + nj * 8;
            #pragma unroll
            for (int half = 0; half < 2; half++) {
                int r = rowBase + mi * 16 + half * 8;
                *(__half2*)(g_wh + (size_t)(br*512 + r) * K3 + t*512 + c) =
                    __halves2half2(__float2half_rn(acc[mi][nj][half*2]),
                                   __float2half_rn(acc[mi][nj][half*2+1]));
            }
        }
    }
}

// =====================================================================
// prep_all: one launch for all converts.
// =====================================================================
#define PB_WPROJ 1024
#define PB_X     32768
#define PB_W1T   768
#define PB_W3    9216

__global__ __launch_bounds__(256) void prep_all(const float* __restrict__ x,
                                                const float* __restrict__ wproj,
                                                const float* __restrict__ w1q,
                                                const float* __restrict__ w1k,
                                                const float* __restrict__ w1v,
                                                const float* __restrict__ w3q,
                                                const float* __restrict__ w3k,
                                                const float* __restrict__ w3v) {
    int blk = blockIdx.x;
    int tid = threadIdx.x;
    if (blk < PB_WPROJ) {
        size_t i = (size_t)blk * 256 + tid;
        g_wph[i] = __float2half_rn(wproj[i]);
        return;
    }
    blk -= PB_WPROJ;
    if (blk < PB_X) {
        size_t i = (size_t)blk * 256 + tid;
        float2 v = *(const float2*)(x + i * 2);
        *(__half2*)(g_xh + i * 2) = __halves2half2(__float2half_rn(v.x), __float2half_rn(v.y));
        return;
    }
    blk -= PB_X;
    if (blk < PB_W1T) {
        __shared__ __half tile[32][33];
        int br = blk >> 8;
        int tb = blk & 255;
        int i0 = (tb >> 4) * 32;
        int c0 = (tb & 15) * 32;
        const float* w1 = br == 0 ? w1q : br == 1 ? w1k : w1v;
        int tx = tid & 31, ty = tid >> 5;
        #pragma unroll
        for (int j = 0; j < 32; j += 8)
            tile[ty + j][tx] = __float2half_rn(w1[(size_t)(i0 + ty + j) * 512 + c0 + tx]);
        __syncthreads();
        __half* o = g_w1t + (size_t)br * 262144;
        #pragma unroll
        for (int j = 0; j < 32; j += 8)
            o[(size_t)(c0 + ty + j) * 512 + i0 + tx] = tile[tx][ty + j];
        return;
    }
    blk -= PB_W1T;
    {
        size_t gi = (size_t)blk * 256 + tid;
        int z  = (int)(gi >> 18);
        int oi = (int)(gi & 262143);
        int br = z / 3, t = z - br * 3;
        const float* w3 = br == 0 ? w3q : br == 1 ? w3k : w3v;
        int o = oi >> 9, i = oi & 511;
        g_w3h[gi] = __float2half_rn(w3[(size_t)o * 1536 + i * 3 + t]);
    }
}

// ---------------- launch ----------------
extern "C" void kernel_launch(void* const* d_in, const int* in_sizes, int n_in,
                              void* d_out, int out_size) {
    const float* x     = (const float*)d_in[0];
    const float* w1q   = (const float*)d_in[1];
    const float* w3q   = (const float*)d_in[2];
    const float* w1k   = (const float*)d_in[3];
    const float* w3k   = (const float*)d_in[4];
    const float* w1v   = (const float*)d_in[5];
    const float* w3v   = (const float*)d_in[6];
    const float* wproj = (const float*)d_in[7];
    const float* bproj = (const float*)d_in[8];
    float* y = (float*)d_out;

    cudaFuncSetAttribute(gemm_qkv,       cudaFuncAttributeMaxDynamicSharedMemorySize, Q_SMEM);
    cudaFuncSetAttribute(scores_softmax, cudaFuncAttributeMaxDynamicSharedMemorySize, SS_SMEM);
    cudaFuncSetAttribute(gemm_weff,      cudaFuncAttributeMaxDynamicSharedMemorySize, G1_SMEM);
    cudaFuncSetAttribute(pv_proj,        cudaFuncAttributeMaxDynamicSharedMemorySize, PP_SMEM);

    // prep + weff
    prep_all<<<PB_WPROJ + PB_X + PB_W1T + PB_W3, 256>>>(x, wproj, w1q, w1k, w1v, w3q, w3k, w3v);
    gemm_weff<<<dim3(4, 4, 9), 256, G1_SMEM>>>();

    // QKV: q,k -> g_qkv; v -> g_vt transposed
    gemm_qkv<<<dim3(Nn/256, K3/128, Bb), 256, Q_SMEM>>>();

    // scores + softmax fused -> P fp16
    scores_softmax<<<dim3(Cc/64, Bb), 512, SS_SMEM>>>();

    // PV + proj fused -> y
    pv_proj<<<dim3(Nn/128, Bb), 256, PP_SMEM>>>(bproj, y);
}